// round 15
// baseline (speedup 1.0000x reference)
#include <cuda_runtime.h>
#include <math.h>
#include <stdint.h>

// HAN: S=256 sentences x W=64 words, E=256, HW=HS=256, C=10
#define SN 256
#define WN 64
#define EN 256
#define HWD 256
#define G3 768

typedef unsigned long long ull;

// ---------------- static device scratch ----------------
__device__ float g_xg[2][WN][SN][G3];      // word input gates, time-major
__device__ float g_wordout[SN][WN][512];   // word BiGRU outputs (F 0..255, B 256..511)
__device__ float g_sent[SN][512];          // sentence vectors
__device__ float g_sxg[2][SN][G3];         // sentence input gates
__device__ float g_sentout[SN][512];       // sentence BiGRU outputs
__device__ float g_hbuf[2][2][SN][HWD];    // word rec h exchange [parity][dir][s][u]
__device__ unsigned g_bars[32];            // barrier counters
__device__ uint32_t g_wih_h[2][G3][EN];    // Wih tf32 hi (pre-converted)
__device__ uint32_t g_wih_l[2][G3][EN];    // Wih tf32 lo

// ---------------- helpers ----------------
__device__ __forceinline__ void fma2(ull& d, ull a, ull b) {
    asm("fma.rn.f32x2 %0, %1, %2, %0;" : "+l"(d) : "l"(a), "l"(b));
}
__device__ __forceinline__ float2 asf2(ull v) {
    float2 r; asm("mov.b64 {%0, %1}, %2;" : "=f"(r.x), "=f"(r.y) : "l"(v)); return r;
}
__device__ __forceinline__ ull mkull(float x, float y) {
    ull v; asm("mov.b64 %0, {%1, %2};" : "=l"(v) : "f"(x), "f"(y)); return v;
}
__device__ __forceinline__ float sigf(float x) {
    return __fdividef(1.0f, 1.0f + __expf(-x));
}
__device__ __forceinline__ float tanh_fast(float x) {
    float e = __expf(-2.0f * x);
    return (1.0f - e) * __fdividef(1.0f, 1.0f + e);
}
__device__ __forceinline__ void bar_arrive(unsigned* p) {
    asm volatile("red.release.gpu.add.u32 [%0], %1;" :: "l"(p), "r"(1u) : "memory");
}
__device__ __forceinline__ unsigned bar_poll(const unsigned* p) {
    unsigned v;
    asm volatile("ld.acquire.gpu.u32 %0, [%1];" : "=r"(v) : "l"(p) : "memory");
    return v;
}
__device__ __forceinline__ uint32_t smem_u32(const void* p) {
    uint32_t a;
    asm("{ .reg .u64 t; cvta.to.shared.u64 t, %1; cvt.u32.u64 %0, t; }" : "=r"(a) : "l"(p));
    return a;
}
__device__ __forceinline__ void sts_cluster(uint32_t addr, uint32_t rank, float v) {
    asm volatile(
        "{\n\t.reg .b32 ra;\n\t"
        "mapa.shared::cluster.u32 ra, %0, %1;\n\t"
        "st.shared::cluster.f32 [ra], %2;\n\t}"
        :: "r"(addr), "r"(rank), "f"(v) : "memory");
}
__device__ __forceinline__ uint32_t tf32h(float x) {
    uint32_t r; asm("cvt.rna.tf32.f32 %0, %1;" : "=r"(r) : "f"(x)); return r;
}
__device__ __forceinline__ void mma_tf32(float d[4],
    uint32_t a0, uint32_t a1, uint32_t a2, uint32_t a3, uint32_t b0, uint32_t b1) {
    asm volatile(
        "mma.sync.aligned.m16n8k8.row.col.f32.tf32.tf32.f32 "
        "{%0,%1,%2,%3}, {%4,%5,%6,%7}, {%8,%9}, {%0,%1,%2,%3};"
        : "+f"(d[0]), "+f"(d[1]), "+f"(d[2]), "+f"(d[3])
        : "r"(a0), "r"(a1), "r"(a2), "r"(a3), "r"(b0), "r"(b1));
}

__global__ void k_zero_bars() {
    if (threadIdx.x < 32) g_bars[threadIdx.x] = 0u;
}

// ---------------- kernel 0: pre-convert Wih to tf32 hi/lo ----------------
__global__ void __launch_bounds__(256) k_cvt_wih(
    const float* __restrict__ WihF, const float* __restrict__ WihB)
{
    const int idx = blockIdx.x * 256 + threadIdx.x;   // over 2*768*256
    const int dir = idx / (G3 * EN);
    const int rem = idx % (G3 * EN);
    const float w = (dir ? WihB : WihF)[rem];
    const uint32_t hi = tf32h(w);
    const uint32_t lo = tf32h(w - __uint_as_float(hi));
    g_wih_h[dir][0][rem] = hi;
    g_wih_l[dir][0][rem] = lo;
}

// ---------------- kernel 1: word input gates (gathered GEMM, tf32x3, preconverted B) -------
// grid (24, 256): 24 col tiles of 64 (F 0..767, B 768..1535), one sentence per blockIdx.y
__global__ void __launch_bounds__(256) k_word_gates(
    const int* __restrict__ toks, const float* __restrict__ emb,
    const float* __restrict__ bihF, const float* __restrict__ bihB)
{
    __shared__ float As[64][36];
    __shared__ uint32_t Bh[64][36];
    __shared__ uint32_t Bl[64][36];
    __shared__ int stok[64];
    const int s   = blockIdx.y;
    const int c0  = blockIdx.x * 64;
    const int dir = (c0 >= G3) ? 1 : 0;
    const int gc0 = c0 - dir * G3;
    const float* __restrict__ bih = dir ? bihB : bihF;
    const int tid = threadIdx.x;
    if (tid < 64) stok[tid] = toks[s * WN + tid];
    __syncthreads();
    const int lane = tid & 31;
    const int warp = tid >> 5;
    const int mt = warp & 3;
    const int ng = warp >> 2;
    const int lr = tid >> 3, lk = (tid & 7) << 2;
    const int g4 = lane >> 2, t4 = lane & 3;

    float acc[4][4];
#pragma unroll
    for (int j = 0; j < 4; j++)
#pragma unroll
        for (int c = 0; c < 4; c++) acc[j][c] = 0.0f;

    for (int k0 = 0; k0 < EN; k0 += 32) {
#pragma unroll
        for (int p = 0; p < 2; p++) {
            const int r = p * 32 + lr;
            *(float4*)&As[r][lk] = *(const float4*)&emb[(size_t)stok[r] * EN + k0 + lk];
            *(uint4*)&Bh[r][lk]  = *(const uint4*)&g_wih_h[dir][gc0 + r][k0 + lk];
            *(uint4*)&Bl[r][lk]  = *(const uint4*)&g_wih_l[dir][gc0 + r][k0 + lk];
        }
        __syncthreads();
#pragma unroll
        for (int kk = 0; kk < 32; kk += 8) {
            const int ar = mt * 16 + g4;
            const int ac = kk + t4;
            const float a0 = As[ar][ac],     a1 = As[ar + 8][ac];
            const float a2 = As[ar][ac + 4], a3 = As[ar + 8][ac + 4];
            const uint32_t a0h = tf32h(a0), a1h = tf32h(a1);
            const uint32_t a2h = tf32h(a2), a3h = tf32h(a3);
            const uint32_t a0l = tf32h(a0 - __uint_as_float(a0h));
            const uint32_t a1l = tf32h(a1 - __uint_as_float(a1h));
            const uint32_t a2l = tf32h(a2 - __uint_as_float(a2h));
            const uint32_t a3l = tf32h(a3 - __uint_as_float(a3h));
#pragma unroll
            for (int j = 0; j < 4; j++) {
                const int bn = ng * 32 + j * 8 + g4;
                const int bk = kk + t4;
                const uint32_t b0h = Bh[bn][bk], b1h = Bh[bn][bk + 4];
                const uint32_t b0l = Bl[bn][bk], b1l = Bl[bn][bk + 4];
                mma_tf32(acc[j], a0h, a1h, a2h, a3h, b0h, b1h);
                mma_tf32(acc[j], a0h, a1h, a2h, a3h, b0l, b1l);
                mma_tf32(acc[j], a0l, a1l, a2l, a3l, b0h, b1h);
            }
        }
        __syncthreads();
    }
    const int orow = mt * 16 + g4;
#pragma unroll
    for (int j = 0; j < 4; j++) {
        const int ocl = ng * 32 + j * 8 + t4 * 2;
        const int ocg = gc0 + ocl;
        const float b0 = bih[ocg], b1 = bih[ocg + 1];
        float2 v0 = {acc[j][0] + b0, acc[j][1] + b1};
        float2 v1 = {acc[j][2] + b0, acc[j][3] + b1};
        *(float2*)&g_xg[dir][orow][s][ocg]     = v0;
        *(float2*)&g_xg[dir][orow + 8][s][ocg] = v1;
    }
}

// ---------------- kernel 2: word recurrence (persistent, f32x2, K halved, 256 thr) ----------
__global__ void __launch_bounds__(256) k_word_rec(
    const float* __restrict__ WhhF, const float* __restrict__ WhhB,
    const float* __restrict__ bhhF, const float* __restrict__ bhhB)
{
    extern __shared__ float sm[];
    float* ws  = sm;                 // [2 kh][32 u][388]
    float* hs  = ws + 2 * 32 * 388;  // [32 sents][256]
    float* cb  = hs + 32 * 256;      // [2 kh][128][25] partials
    float* sbh = cb + 2 * 128 * 25;  // [96]
    const int blk = blockIdx.x;
    const int dir = blk >> 6;
    const int st  = (blk >> 3) & 7;
    const int ut  = blk & 7;
    const int u0  = ut * 32;
    const int grp = dir * 8 + st;
    const float* __restrict__ Whh = dir ? WhhB : WhhF;
    const float* __restrict__ bhh = dir ? bhhB : bhhF;
    const int tid = threadIdx.x;
    const int u  = tid & 31;
    const int sq = (tid >> 5) & 3;
    const int kh = tid >> 7;

    for (int idx = tid * 4; idx < 2 * 32 * 384; idx += 1024) {
        const int khh = idx / 12288;
        const int r2  = idx % 12288;
        const int uu  = r2 / 384;
        const int rem = r2 % 384;
        const int g = rem >> 7, kk = rem & 127;
        *(float4*)&ws[(khh * 32 + uu) * 388 + rem] =
            *(const float4*)&Whh[(size_t)(g * 256 + u0 + uu) * 256 + khh * 128 + kk];
    }
    if (tid < 96) sbh[tid] = bhh[(tid >> 5) * 256 + u0 + (tid & 31)];
    for (int i = tid; i < 32 * 256; i += 256) hs[i] = 0.0f;
    __syncthreads();

    const float* wku = &ws[(kh * 32 + u) * 388];
    const float bh_r = sbh[u], bh_z = sbh[32 + u], bh_n = sbh[64 + u];
    const int uc = u0 + u;
    const int kb = kh * 128;
    const int jb = kh * 4;

    for (int t = 0; t < 64; t++) {
        const int tt = dir ? (63 - t) : t;
        float xr[4], xz[4], xn[4];
#pragma unroll
        for (int jj = 0; jj < 4; jj++) {
            const int s = st * 32 + sq * 8 + jb + jj;
            xr[jj] = g_xg[dir][tt][s][uc];
            xz[jj] = g_xg[dir][tt][s][256 + uc];
            xn[jj] = g_xg[dir][tt][s][512 + uc];
        }
        ull acc[3][8];
#pragma unroll
        for (int g = 0; g < 3; g++)
#pragma unroll
            for (int j = 0; j < 8; j++) acc[g][j] = 0ull;

#pragma unroll 4
        for (int kk = 0; kk < 128; kk += 4) {
            ulonglong2 w0 = *(const ulonglong2*)&wku[kk];
            ulonglong2 w1 = *(const ulonglong2*)&wku[128 + kk];
            ulonglong2 w2 = *(const ulonglong2*)&wku[256 + kk];
#pragma unroll
            for (int j = 0; j < 8; j++) {
                ulonglong2 h2 = *(const ulonglong2*)&hs[(sq * 8 + j) * 256 + kb + kk];
                fma2(acc[0][j], w0.x, h2.x); fma2(acc[0][j], w0.y, h2.y);
                fma2(acc[1][j], w1.x, h2.x); fma2(acc[1][j], w1.y, h2.y);
                fma2(acc[2][j], w2.x, h2.x); fma2(acc[2][j], w2.y, h2.y);
            }
        }
        {
            float* row = &cb[kh * 3200 + (sq * 32 + u) * 25];
#pragma unroll
            for (int g = 0; g < 3; g++)
#pragma unroll
                for (int j = 0; j < 8; j++) {
                    float2 f = asf2(acc[g][j]);
                    row[g * 8 + j] = f.x + f.y;
                }
        }
        __syncthreads();
        const int par = (t + 1) & 1;
        {
            const float* r0 = &cb[(sq * 32 + u) * 25];
            const float* r1 = &cb[3200 + (sq * 32 + u) * 25];
#pragma unroll
            for (int jj = 0; jj < 4; jj++) {
                const int j  = jb + jj;
                const int sl = sq * 8 + j;
                const int s  = st * 32 + sl;
                const float pr = r0[j]      + r1[j];
                const float pz = r0[8 + j]  + r1[8 + j];
                const float pn = r0[16 + j] + r1[16 + j];
                const float r = sigf(xr[jj] + pr + bh_r);
                const float z = sigf(xz[jj] + pz + bh_z);
                const float n = tanh_fast(xn[jj] + r * (pn + bh_n));
                const float hold = hs[sl * 256 + uc];
                const float hnew = (1.0f - z) * n + z * hold;
                __stcg(&g_hbuf[par][dir][s][uc], hnew);
                g_wordout[s][tt][dir * 256 + uc] = hnew;
            }
        }
        __syncthreads();
        if (tid == 0) {
            bar_arrive(&g_bars[grp]);
            const unsigned tgt = 8u * (unsigned)(t + 1);
            while (bar_poll(&g_bars[grp]) < tgt) { }
        }
        __syncthreads();
        if (t < 63) {
            const float* src = &g_hbuf[par][dir][st * 32][0];
            for (int i = tid * 4; i < 32 * 256; i += 1024)
                *(float4*)&hs[i] = __ldcg((const float4*)(src + i));
            __syncthreads();
        }
    }
}

// ---------------- kernel 3: word attention pool -> sentence vectors ----------------
__global__ void __launch_bounds__(256) k_word_attn(
    const float* __restrict__ attw, const float* __restrict__ attb)
{
    __shared__ float sc[64];
    const int s = blockIdx.x;
    const int tid = threadIdx.x, wp = tid >> 5, ln = tid & 31;
    const float bb = attb[0];
    for (int w = wp; w < 64; w += 8) {
        const float* op = &g_wordout[s][w][0];
        float d = 0.0f;
#pragma unroll
        for (int i = 0; i < 4; i++) {
            float4 o = *(const float4*)&op[ln * 16 + i * 4];
            float4 a = *(const float4*)&attw[ln * 16 + i * 4];
            d += o.x * a.x + o.y * a.y + o.z * a.z + o.w * a.w;
        }
#pragma unroll
        for (int off = 16; off > 0; off >>= 1) d += __shfl_xor_sync(0xffffffffu, d, off);
        if (ln == 0) sc[w] = tanhf(d + bb);
    }
    __syncthreads();
    if (tid < 32) {
        float a0 = sc[tid], a1 = sc[tid + 32];
        float m = fmaxf(a0, a1);
#pragma unroll
        for (int off = 16; off > 0; off >>= 1) m = fmaxf(m, __shfl_xor_sync(0xffffffffu, m, off));
        float e0 = expf(a0 - m), e1 = expf(a1 - m);
        float ssum = e0 + e1;
#pragma unroll
        for (int off = 16; off > 0; off >>= 1) ssum += __shfl_xor_sync(0xffffffffu, ssum, off);
        sc[tid] = e0 / ssum; sc[tid + 32] = e1 / ssum;
    }
    __syncthreads();
    float acc0 = 0.0f, acc1 = 0.0f;
    for (int w = 0; w < 64; w++) {
        const float a = sc[w];
        acc0 += a * g_wordout[s][w][tid];
        acc1 += a * g_wordout[s][w][tid + 256];
    }
    g_sent[s][tid] = acc0;
    g_sent[s][tid + 256] = acc1;
}

// ---------------- kernel 4: sentence input gates (SGEMM K=512, f32x2) ----------------
__global__ void __launch_bounds__(256) k_sent_gates(
    const float* __restrict__ WihF, const float* __restrict__ WihB,
    const float* __restrict__ bihF, const float* __restrict__ bihB)
{
    __shared__ float As[64][36];
    __shared__ float Bs[64][36];
    const int s0  = blockIdx.y * 64;
    const int c0  = blockIdx.x * 64;
    const int dir = (c0 >= G3) ? 1 : 0;
    const int gc0 = c0 - dir * G3;
    const float* __restrict__ Wih = dir ? WihB : WihF;
    const float* __restrict__ bih = dir ? bihB : bihF;
    const int tid = threadIdx.x;
    const int tx = tid & 15, ty = tid >> 4;
    const int lr = tid >> 3, lk = (tid & 7) << 2;
    ull acc2[4][4];
#pragma unroll
    for (int i = 0; i < 4; i++)
#pragma unroll
        for (int j = 0; j < 4; j++) acc2[i][j] = 0ull;

    for (int k0 = 0; k0 < 512; k0 += 32) {
#pragma unroll
        for (int p = 0; p < 2; p++) {
            const int r = p * 32 + lr;
            *(float4*)&As[r][lk] = *(const float4*)&g_sent[s0 + r][k0 + lk];
            *(float4*)&Bs[r][lk] = *(const float4*)&Wih[(size_t)(gc0 + r) * 512 + k0 + lk];
        }
        __syncthreads();
#pragma unroll
        for (int k = 0; k < 32; k += 4) {
            ulonglong2 a_[4], b_[4];
#pragma unroll
            for (int i = 0; i < 4; i++) a_[i] = *(const ulonglong2*)&As[ty * 4 + i][k];
#pragma unroll
            for (int j = 0; j < 4; j++) b_[j] = *(const ulonglong2*)&Bs[tx + 16 * j][k];
#pragma unroll
            for (int i = 0; i < 4; i++)
#pragma unroll
                for (int j = 0; j < 4; j++) {
                    fma2(acc2[i][j], a_[i].x, b_[j].x);
                    fma2(acc2[i][j], a_[i].y, b_[j].y);
                }
        }
        __syncthreads();
    }
#pragma unroll
    for (int j = 0; j < 4; j++) {
        const int cgl = gc0 + tx + 16 * j;
        const float bj = bih[cgl];
#pragma unroll
        for (int i = 0; i < 4; i++) {
            float2 f = asf2(acc2[i][j]);
            g_sxg[dir][s0 + ty * 4 + i][cgl] = f.x + f.y + bj;
        }
    }
}

// ---------------- kernel 5: sentence recurrence (reg weights, cluster of 4, DSMEM push) ----
// grid 8 = dir(2) x unit-tile(4 x 64 units) = 2 clusters of 4, 768 threads
// thread map: r = tid>>2 (row 0..191: gate = r/64, unit = u0 + r%64), q = tid&3 (K-quarter)
__global__ void __launch_bounds__(768) __cluster_dims__(4, 1, 1) k_sent_rec(
    const float* __restrict__ WhhF, const float* __restrict__ WhhB,
    const float* __restrict__ bhhF, const float* __restrict__ bhhB)
{
    __shared__ __align__(16) float hb[2][272];  // h, padded: u -> (u>>6)*68 + (u&63)
    __shared__ float gv[192];                   // gate values: r = gate*64 + ulocal
    const int dir = blockIdx.x >> 2;
    const int ut  = blockIdx.x & 3;
    const int u0  = ut * 64;
    const float* __restrict__ Whh = dir ? WhhB : WhhF;
    const float* __restrict__ bhh = dir ? bhhB : bhhF;
    const int tid = threadIdx.x;
    const int r = tid >> 2;
    const int q = tid & 3;
    const int row = (r >> 6) * 256 + u0 + (r & 63);
    const uint32_t hb_base = smem_u32(hb);

    // this thread's 64 weights (K-quarter q of the row) in registers
    ull wreg[32];
    {
        const float4* wsrc = (const float4*)&Whh[(size_t)row * 256 + q * 64];
#pragma unroll
        for (int i = 0; i < 16; i++) {
            float4 v = wsrc[i];
            wreg[2 * i]     = mkull(v.x, v.y);
            wreg[2 * i + 1] = mkull(v.z, v.w);
        }
    }
    const float bh = bhh[row];
    for (int k = tid; k < 544; k += 768) hb[0][k] = 0.0f;   // zero both buffers
    __syncthreads();
    asm volatile("barrier.cluster.arrive.aligned;" ::: "memory");
    asm volatile("barrier.cluster.wait.aligned;" ::: "memory");

    for (int t = 0; t < 256; t++) {
        const int tt = dir ? (255 - t) : t;
        const int cur = t & 1, nxt = cur ^ 1;
        float xr = 0.0f, xz = 0.0f, xn = 0.0f;
        if (tid < 64) {
            const int u = u0 + tid;
            xr = g_sxg[dir][tt][u];
            xz = g_sxg[dir][tt][256 + u];
            xn = g_sxg[dir][tt][512 + u];
        }
        ull acc2 = 0ull;
        const float* hq = &hb[cur][q * 68];   // K-quarter q = units q*64..q*64+63 (pad-aligned)
#pragma unroll
        for (int i = 0; i < 16; i++) {
            ulonglong2 h2 = *(const ulonglong2*)&hq[i * 4];
            fma2(acc2, h2.x, wreg[2 * i]);
            fma2(acc2, h2.y, wreg[2 * i + 1]);
        }
        float2 fa = asf2(acc2);
        float s = fa.x + fa.y;
        s += __shfl_xor_sync(0xffffffffu, s, 1);
        s += __shfl_xor_sync(0xffffffffu, s, 2);
        if (q == 0) gv[r] = s + bh;
        __syncthreads();                 // gv ready; all reads of hb[cur] complete
        if (tid < 64) {
            const int u = u0 + tid;
            const float hold = hb[cur][(u >> 6) * 68 + (u & 63)];
            const float rr = sigf(xr + gv[tid]);
            const float zz = sigf(xz + gv[64 + tid]);
            const float nn = tanh_fast(xn + rr * gv[128 + tid]);
            const float hnew = (1.0f - zz) * nn + zz * hold;
            g_sentout[tt][dir * 256 + u] = hnew;
            if (t < 255) {
                const uint32_t adr =
                    hb_base + (uint32_t)(nxt * 272 + (u >> 6) * 68 + (u & 63)) * 4u;
#pragma unroll
                for (int c = 0; c < 4; c++) sts_cluster(adr, (uint32_t)c, hnew);
            }
        }
        asm volatile("barrier.cluster.arrive.aligned;" ::: "memory");
        asm volatile("barrier.cluster.wait.aligned;" ::: "memory");
    }
}

// ---------------- kernel 6: sentence attention + classifier + softmax ----------------
__global__ void __launch_bounds__(256) k_doc(
    const float* __restrict__ attw, const float* __restrict__ attb,
    const float* __restrict__ clsW, const float* __restrict__ clsB,
    float* __restrict__ out)
{
    __shared__ float sc[256];
    __shared__ float red[8];
    __shared__ float docv[512];
    __shared__ float lg[10];
    const int tid = threadIdx.x, wp = tid >> 5, ln = tid & 31;
    const float bb = attb[0];
    for (int s = wp; s < 256; s += 8) {
        const float* op = &g_sentout[s][0];
        float d = 0.0f;
#pragma unroll
        for (int i = 0; i < 4; i++) {
            float4 o = *(const float4*)&op[ln * 16 + i * 4];
            float4 a = *(const float4*)&attw[ln * 16 + i * 4];
            d += o.x * a.x + o.y * a.y + o.z * a.z + o.w * a.w;
        }
#pragma unroll
        for (int off = 16; off > 0; off >>= 1) d += __shfl_xor_sync(0xffffffffu, d, off);
        if (ln == 0) sc[s] = tanhf(d + bb);
    }
    __syncthreads();
    float v = sc[tid];
    float m = v;
#pragma unroll
    for (int off = 16; off > 0; off >>= 1) m = fmaxf(m, __shfl_xor_sync(0xffffffffu, m, off));
    if (ln == 0) red[wp] = m;
    __syncthreads();
    if (tid < 8) {
        float mm = red[tid];
#pragma unroll
        for (int off = 4; off > 0; off >>= 1) mm = fmaxf(mm, __shfl_xor_sync(0xffu, mm, off));
        red[tid] = mm;
    }
    __syncthreads();
    const float gm = red[0];
    float e = expf(v - gm);
    float ssum = e;
#pragma unroll
    for (int off = 16; off > 0; off >>= 1) ssum += __shfl_xor_sync(0xffffffffu, ssum, off);
    __syncthreads();
    if (ln == 0) red[wp] = ssum;
    __syncthreads();
    if (tid < 8) {
        float s2 = red[tid];
#pragma unroll
        for (int off = 4; off > 0; off >>= 1) s2 += __shfl_xor_sync(0xffu, s2, off);
        red[tid] = s2;
    }
    __syncthreads();
    const float tot = red[0];
    sc[tid] = e / tot;
    __syncthreads();
    float a0 = 0.0f, a1 = 0.0f;
    for (int s = 0; s < 256; s++) {
        const float a = sc[s];
        a0 += a * g_sentout[s][tid];
        a1 += a * g_sentout[s][tid + 256];
    }
    docv[tid] = a0; docv[tid + 256] = a1;
    __syncthreads();
    for (int o = wp; o < 10; o += 8) {
        const float* wr = &clsW[o * 512];
        float d = 0.0f;
#pragma unroll
        for (int i = 0; i < 4; i++) {
            float4 x = *(const float4*)&docv[ln * 16 + i * 4];
            float4 w = *(const float4*)&wr[ln * 16 + i * 4];
            d += x.x * w.x + x.y * w.y + x.z * w.z + x.w * w.w;
        }
#pragma unroll
        for (int off = 16; off > 0; off >>= 1) d += __shfl_xor_sync(0xffffffffu, d, off);
        if (ln == 0) lg[o] = d + clsB[o];
    }
    __syncthreads();
    if (tid == 0) {
        float mm = lg[0];
        for (int i = 1; i < 10; i++) mm = fmaxf(mm, lg[i]);
        float s2 = 0.0f;
        float ee[10];
        for (int i = 0; i < 10; i++) { ee[i] = expf(lg[i] - mm); s2 += ee[i]; }
        for (int i = 0; i < 10; i++) out[i] = ee[i] / s2;
    }
}

// ---------------- launch ----------------
extern "C" void kernel_launch(void* const* d_in, const int* in_sizes, int n_in,
                              void* d_out, int out_size) {
    const int*   toks  = (const int*)d_in[0];
    const float* emb   = (const float*)d_in[1];
    const float* wWihF = (const float*)d_in[2];
    const float* wWhhF = (const float*)d_in[3];
    const float* wBihF = (const float*)d_in[4];
    const float* wBhhF = (const float*)d_in[5];
    const float* wWihB = (const float*)d_in[6];
    const float* wWhhB = (const float*)d_in[7];
    const float* wBihB = (const float*)d_in[8];
    const float* wBhhB = (const float*)d_in[9];
    const float* sWihF = (const float*)d_in[10];
    const float* sWhhF = (const float*)d_in[11];
    const float* sBihF = (const float*)d_in[12];
    const float* sBhhF = (const float*)d_in[13];
    const float* sWihB = (const float*)d_in[14];
    const float* sWhhB = (const float*)d_in[15];
    const float* sBihB = (const float*)d_in[16];
    const float* sBhhB = (const float*)d_in[17];
    const float* wAttW = (const float*)d_in[18];
    const float* wAttB = (const float*)d_in[19];
    const float* sAttW = (const float*)d_in[20];
    const float* sAttB = (const float*)d_in[21];
    const float* clsW  = (const float*)d_in[22];
    const float* clsB  = (const float*)d_in[23];
    float* out = (float*)d_out;

    const int WREC_SMEM = (2 * 32 * 388 + 32 * 256 + 2 * 128 * 25 + 96) * 4;  // 158080
    cudaFuncSetAttribute(k_word_rec, cudaFuncAttributeMaxDynamicSharedMemorySize, WREC_SMEM);

    k_zero_bars<<<1, 32>>>();
    k_zero_bars<<<1, 32>>>();                        // dummy: keeps gates at ncu slot (idx 3)
    k_cvt_wih<<<2 * G3 * EN / 256, 256>>>(wWihF, wWihB);
    dim3 g1(24, 256);
    k_word_gates<<<g1, 256>>>(toks, emb, wBihF, wBihB);
    k_word_rec<<<128, 256, WREC_SMEM>>>(wWhhF, wWhhB, wBhhF, wBhhB);
    k_word_attn<<<256, 256>>>(wAttW, wAttB);
    dim3 g2(24, 4);
    k_sent_gates<<<g2, 256>>>(sWihF, sWihB, sBihF, sBihB);
    k_sent_rec<<<8, 768>>>(sWhhF, sWhhB, sBhhF, sBhhB);
    k_doc<<<1, 256>>>(sAttW, sAttB, clsW, clsB, out);
}

// round 16
// speedup vs baseline: 1.1074x; 1.1074x over previous
#include <cuda_runtime.h>
#include <math.h>
#include <stdint.h>

// HAN: S=256 sentences x W=64 words, E=256, HW=HS=256, C=10
#define SN 256
#define WN 64
#define EN 256
#define HWD 256
#define G3 768

typedef unsigned long long ull;

// ---------------- static device scratch ----------------
__device__ float g_xg[2][WN][SN][G3];      // word input gates, time-major
__device__ float g_wordout[SN][WN][512];   // word BiGRU outputs (F 0..255, B 256..511)
__device__ float g_sent[SN][512];          // sentence vectors
__device__ float g_sxg[2][SN][G3];         // sentence input gates
__device__ float g_sentout[SN][512];       // sentence BiGRU outputs
__device__ float g_hbuf[2][2][SN][HWD];    // word rec h exchange [parity][dir][s][u]
__device__ unsigned g_bars[32];            // barrier counters
__device__ uint32_t g_wih_h[2][G3][EN];    // Wih tf32 hi (pre-converted)
__device__ uint32_t g_wih_l[2][G3][EN];    // Wih tf32 lo

// ---------------- helpers ----------------
__device__ __forceinline__ void fma2(ull& d, ull a, ull b) {
    asm("fma.rn.f32x2 %0, %1, %2, %0;" : "+l"(d) : "l"(a), "l"(b));
}
__device__ __forceinline__ float2 asf2(ull v) {
    float2 r; asm("mov.b64 {%0, %1}, %2;" : "=f"(r.x), "=f"(r.y) : "l"(v)); return r;
}
__device__ __forceinline__ ull mkull(float x, float y) {
    ull v; asm("mov.b64 %0, {%1, %2};" : "=l"(v) : "f"(x), "f"(y)); return v;
}
__device__ __forceinline__ float sigf(float x) {
    return __fdividef(1.0f, 1.0f + __expf(-x));
}
__device__ __forceinline__ float tanh_fast(float x) {
    float e = __expf(-2.0f * x);
    return (1.0f - e) * __fdividef(1.0f, 1.0f + e);
}
__device__ __forceinline__ void bar_arrive(unsigned* p) {
    asm volatile("red.release.gpu.add.u32 [%0], %1;" :: "l"(p), "r"(1u) : "memory");
}
__device__ __forceinline__ unsigned bar_poll(const unsigned* p) {
    unsigned v;
    asm volatile("ld.acquire.gpu.u32 %0, [%1];" : "=r"(v) : "l"(p) : "memory");
    return v;
}
__device__ __forceinline__ uint32_t smem_u32(const void* p) {
    uint32_t a;
    asm("{ .reg .u64 t; cvta.to.shared.u64 t, %1; cvt.u32.u64 %0, t; }" : "=r"(a) : "l"(p));
    return a;
}
__device__ __forceinline__ void sts_cluster(uint32_t addr, uint32_t rank, float v) {
    asm volatile(
        "{\n\t.reg .b32 ra;\n\t"
        "mapa.shared::cluster.u32 ra, %0, %1;\n\t"
        "st.shared::cluster.f32 [ra], %2;\n\t}"
        :: "r"(addr), "r"(rank), "f"(v) : "memory");
}
__device__ __forceinline__ uint32_t tf32h(float x) {
    uint32_t r; asm("cvt.rna.tf32.f32 %0, %1;" : "=r"(r) : "f"(x)); return r;
}
__device__ __forceinline__ void mma_tf32(float d[4],
    uint32_t a0, uint32_t a1, uint32_t a2, uint32_t a3, uint32_t b0, uint32_t b1) {
    asm volatile(
        "mma.sync.aligned.m16n8k8.row.col.f32.tf32.tf32.f32 "
        "{%0,%1,%2,%3}, {%4,%5,%6,%7}, {%8,%9}, {%0,%1,%2,%3};"
        : "+f"(d[0]), "+f"(d[1]), "+f"(d[2]), "+f"(d[3])
        : "r"(a0), "r"(a1), "r"(a2), "r"(a3), "r"(b0), "r"(b1));
}

__global__ void k_zero_bars() {
    if (threadIdx.x < 32) g_bars[threadIdx.x] = 0u;
}

// ---------------- kernel 0: pre-convert Wih to tf32 hi/lo ----------------
__global__ void __launch_bounds__(256) k_cvt_wih(
    const float* __restrict__ WihF, const float* __restrict__ WihB)
{
    const int idx = blockIdx.x * 256 + threadIdx.x;   // over 2*768*256
    const int dir = idx / (G3 * EN);
    const int rem = idx % (G3 * EN);
    const float w = (dir ? WihB : WihF)[rem];
    const uint32_t hi = tf32h(w);
    const uint32_t lo = tf32h(w - __uint_as_float(hi));
    g_wih_h[dir][0][rem] = hi;
    g_wih_l[dir][0][rem] = lo;
}

// ---------------- kernel 1: word input gates (gathered GEMM, tf32x3, preconverted B) -------
// grid (24, 256): 24 col tiles of 64 (F 0..767, B 768..1535), one sentence per blockIdx.y
__global__ void __launch_bounds__(256) k_word_gates(
    const int* __restrict__ toks, const float* __restrict__ emb,
    const float* __restrict__ bihF, const float* __restrict__ bihB)
{
    __shared__ float As[64][36];
    __shared__ uint32_t Bh[64][36];
    __shared__ uint32_t Bl[64][36];
    __shared__ int stok[64];
    const int s   = blockIdx.y;
    const int c0  = blockIdx.x * 64;
    const int dir = (c0 >= G3) ? 1 : 0;
    const int gc0 = c0 - dir * G3;
    const float* __restrict__ bih = dir ? bihB : bihF;
    const int tid = threadIdx.x;
    if (tid < 64) stok[tid] = toks[s * WN + tid];
    __syncthreads();
    const int lane = tid & 31;
    const int warp = tid >> 5;
    const int mt = warp & 3;
    const int ng = warp >> 2;
    const int lr = tid >> 3, lk = (tid & 7) << 2;
    const int g4 = lane >> 2, t4 = lane & 3;

    float acc[4][4];
#pragma unroll
    for (int j = 0; j < 4; j++)
#pragma unroll
        for (int c = 0; c < 4; c++) acc[j][c] = 0.0f;

    for (int k0 = 0; k0 < EN; k0 += 32) {
#pragma unroll
        for (int p = 0; p < 2; p++) {
            const int r = p * 32 + lr;
            *(float4*)&As[r][lk] = *(const float4*)&emb[(size_t)stok[r] * EN + k0 + lk];
            *(uint4*)&Bh[r][lk]  = *(const uint4*)&g_wih_h[dir][gc0 + r][k0 + lk];
            *(uint4*)&Bl[r][lk]  = *(const uint4*)&g_wih_l[dir][gc0 + r][k0 + lk];
        }
        __syncthreads();
#pragma unroll
        for (int kk = 0; kk < 32; kk += 8) {
            const int ar = mt * 16 + g4;
            const int ac = kk + t4;
            const float a0 = As[ar][ac],     a1 = As[ar + 8][ac];
            const float a2 = As[ar][ac + 4], a3 = As[ar + 8][ac + 4];
            const uint32_t a0h = tf32h(a0), a1h = tf32h(a1);
            const uint32_t a2h = tf32h(a2), a3h = tf32h(a3);
            const uint32_t a0l = tf32h(a0 - __uint_as_float(a0h));
            const uint32_t a1l = tf32h(a1 - __uint_as_float(a1h));
            const uint32_t a2l = tf32h(a2 - __uint_as_float(a2h));
            const uint32_t a3l = tf32h(a3 - __uint_as_float(a3h));
#pragma unroll
            for (int j = 0; j < 4; j++) {
                const int bn = ng * 32 + j * 8 + g4;
                const int bk = kk + t4;
                const uint32_t b0h = Bh[bn][bk], b1h = Bh[bn][bk + 4];
                const uint32_t b0l = Bl[bn][bk], b1l = Bl[bn][bk + 4];
                mma_tf32(acc[j], a0h, a1h, a2h, a3h, b0h, b1h);
                mma_tf32(acc[j], a0h, a1h, a2h, a3h, b0l, b1l);
                mma_tf32(acc[j], a0l, a1l, a2l, a3l, b0h, b1h);
            }
        }
        __syncthreads();
    }
    const int orow = mt * 16 + g4;
#pragma unroll
    for (int j = 0; j < 4; j++) {
        const int ocl = ng * 32 + j * 8 + t4 * 2;
        const int ocg = gc0 + ocl;
        const float b0 = bih[ocg], b1 = bih[ocg + 1];
        float2 v0 = {acc[j][0] + b0, acc[j][1] + b1};
        float2 v1 = {acc[j][2] + b0, acc[j][3] + b1};
        *(float2*)&g_xg[dir][orow][s][ocg]     = v0;
        *(float2*)&g_xg[dir][orow + 8][s][ocg] = v1;
    }
}

// ---------------- kernel 2: word recurrence (persistent, f32x2, K halved, 256 thr) ----------
__global__ void __launch_bounds__(256) k_word_rec(
    const float* __restrict__ WhhF, const float* __restrict__ WhhB,
    const float* __restrict__ bhhF, const float* __restrict__ bhhB)
{
    extern __shared__ float sm[];
    float* ws  = sm;                 // [2 kh][32 u][388]
    float* hs  = ws + 2 * 32 * 388;  // [32 sents][256]
    float* cb  = hs + 32 * 256;      // [2 kh][128][25] partials
    float* sbh = cb + 2 * 128 * 25;  // [96]
    const int blk = blockIdx.x;
    const int dir = blk >> 6;
    const int st  = (blk >> 3) & 7;
    const int ut  = blk & 7;
    const int u0  = ut * 32;
    const int grp = dir * 8 + st;
    const float* __restrict__ Whh = dir ? WhhB : WhhF;
    const float* __restrict__ bhh = dir ? bhhB : bhhF;
    const int tid = threadIdx.x;
    const int u  = tid & 31;
    const int sq = (tid >> 5) & 3;
    const int kh = tid >> 7;

    for (int idx = tid * 4; idx < 2 * 32 * 384; idx += 1024) {
        const int khh = idx / 12288;
        const int r2  = idx % 12288;
        const int uu  = r2 / 384;
        const int rem = r2 % 384;
        const int g = rem >> 7, kk = rem & 127;
        *(float4*)&ws[(khh * 32 + uu) * 388 + rem] =
            *(const float4*)&Whh[(size_t)(g * 256 + u0 + uu) * 256 + khh * 128 + kk];
    }
    if (tid < 96) sbh[tid] = bhh[(tid >> 5) * 256 + u0 + (tid & 31)];
    for (int i = tid; i < 32 * 256; i += 256) hs[i] = 0.0f;
    __syncthreads();

    const float* wku = &ws[(kh * 32 + u) * 388];
    const float bh_r = sbh[u], bh_z = sbh[32 + u], bh_n = sbh[64 + u];
    const int uc = u0 + u;
    const int kb = kh * 128;
    const int jb = kh * 4;

    for (int t = 0; t < 64; t++) {
        const int tt = dir ? (63 - t) : t;
        float xr[4], xz[4], xn[4];
#pragma unroll
        for (int jj = 0; jj < 4; jj++) {
            const int s = st * 32 + sq * 8 + jb + jj;
            xr[jj] = g_xg[dir][tt][s][uc];
            xz[jj] = g_xg[dir][tt][s][256 + uc];
            xn[jj] = g_xg[dir][tt][s][512 + uc];
        }
        ull acc[3][8];
#pragma unroll
        for (int g = 0; g < 3; g++)
#pragma unroll
            for (int j = 0; j < 8; j++) acc[g][j] = 0ull;

#pragma unroll 4
        for (int kk = 0; kk < 128; kk += 4) {
            ulonglong2 w0 = *(const ulonglong2*)&wku[kk];
            ulonglong2 w1 = *(const ulonglong2*)&wku[128 + kk];
            ulonglong2 w2 = *(const ulonglong2*)&wku[256 + kk];
#pragma unroll
            for (int j = 0; j < 8; j++) {
                ulonglong2 h2 = *(const ulonglong2*)&hs[(sq * 8 + j) * 256 + kb + kk];
                fma2(acc[0][j], w0.x, h2.x); fma2(acc[0][j], w0.y, h2.y);
                fma2(acc[1][j], w1.x, h2.x); fma2(acc[1][j], w1.y, h2.y);
                fma2(acc[2][j], w2.x, h2.x); fma2(acc[2][j], w2.y, h2.y);
            }
        }
        {
            float* row = &cb[kh * 3200 + (sq * 32 + u) * 25];
#pragma unroll
            for (int g = 0; g < 3; g++)
#pragma unroll
                for (int j = 0; j < 8; j++) {
                    float2 f = asf2(acc[g][j]);
                    row[g * 8 + j] = f.x + f.y;
                }
        }
        __syncthreads();
        const int par = (t + 1) & 1;
        {
            const float* r0 = &cb[(sq * 32 + u) * 25];
            const float* r1 = &cb[3200 + (sq * 32 + u) * 25];
#pragma unroll
            for (int jj = 0; jj < 4; jj++) {
                const int j  = jb + jj;
                const int sl = sq * 8 + j;
                const int s  = st * 32 + sl;
                const float pr = r0[j]      + r1[j];
                const float pz = r0[8 + j]  + r1[8 + j];
                const float pn = r0[16 + j] + r1[16 + j];
                const float r = sigf(xr[jj] + pr + bh_r);
                const float z = sigf(xz[jj] + pz + bh_z);
                const float n = tanh_fast(xn[jj] + r * (pn + bh_n));
                const float hold = hs[sl * 256 + uc];
                const float hnew = (1.0f - z) * n + z * hold;
                __stcg(&g_hbuf[par][dir][s][uc], hnew);
                g_wordout[s][tt][dir * 256 + uc] = hnew;
            }
        }
        __syncthreads();
        if (tid == 0) {
            bar_arrive(&g_bars[grp]);
            const unsigned tgt = 8u * (unsigned)(t + 1);
            while (bar_poll(&g_bars[grp]) < tgt) { }
        }
        __syncthreads();
        if (t < 63) {
            const float* src = &g_hbuf[par][dir][st * 32][0];
            for (int i = tid * 4; i < 32 * 256; i += 1024)
                *(float4*)&hs[i] = __ldcg((const float4*)(src + i));
            __syncthreads();
        }
    }
}

// ---------------- kernel 3: word attention pool -> sentence vectors ----------------
__global__ void __launch_bounds__(256) k_word_attn(
    const float* __restrict__ attw, const float* __restrict__ attb)
{
    __shared__ float sc[64];
    const int s = blockIdx.x;
    const int tid = threadIdx.x, wp = tid >> 5, ln = tid & 31;
    const float bb = attb[0];
    for (int w = wp; w < 64; w += 8) {
        const float* op = &g_wordout[s][w][0];
        float d = 0.0f;
#pragma unroll
        for (int i = 0; i < 4; i++) {
            float4 o = *(const float4*)&op[ln * 16 + i * 4];
            float4 a = *(const float4*)&attw[ln * 16 + i * 4];
            d += o.x * a.x + o.y * a.y + o.z * a.z + o.w * a.w;
        }
#pragma unroll
        for (int off = 16; off > 0; off >>= 1) d += __shfl_xor_sync(0xffffffffu, d, off);
        if (ln == 0) sc[w] = tanhf(d + bb);
    }
    __syncthreads();
    if (tid < 32) {
        float a0 = sc[tid], a1 = sc[tid + 32];
        float m = fmaxf(a0, a1);
#pragma unroll
        for (int off = 16; off > 0; off >>= 1) m = fmaxf(m, __shfl_xor_sync(0xffffffffu, m, off));
        float e0 = expf(a0 - m), e1 = expf(a1 - m);
        float ssum = e0 + e1;
#pragma unroll
        for (int off = 16; off > 0; off >>= 1) ssum += __shfl_xor_sync(0xffffffffu, ssum, off);
        sc[tid] = e0 / ssum; sc[tid + 32] = e1 / ssum;
    }
    __syncthreads();
    float acc0 = 0.0f, acc1 = 0.0f;
    for (int w = 0; w < 64; w++) {
        const float a = sc[w];
        acc0 += a * g_wordout[s][w][tid];
        acc1 += a * g_wordout[s][w][tid + 256];
    }
    g_sent[s][tid] = acc0;
    g_sent[s][tid + 256] = acc1;
}

// ---------------- kernel 4: sentence input gates (SGEMM K=512, f32x2) ----------------
__global__ void __launch_bounds__(256) k_sent_gates(
    const float* __restrict__ WihF, const float* __restrict__ WihB,
    const float* __restrict__ bihF, const float* __restrict__ bihB)
{
    __shared__ float As[64][36];
    __shared__ float Bs[64][36];
    const int s0  = blockIdx.y * 64;
    const int c0  = blockIdx.x * 64;
    const int dir = (c0 >= G3) ? 1 : 0;
    const int gc0 = c0 - dir * G3;
    const float* __restrict__ Wih = dir ? WihB : WihF;
    const float* __restrict__ bih = dir ? bihB : bihF;
    const int tid = threadIdx.x;
    const int tx = tid & 15, ty = tid >> 4;
    const int lr = tid >> 3, lk = (tid & 7) << 2;
    ull acc2[4][4];
#pragma unroll
    for (int i = 0; i < 4; i++)
#pragma unroll
        for (int j = 0; j < 4; j++) acc2[i][j] = 0ull;

    for (int k0 = 0; k0 < 512; k0 += 32) {
#pragma unroll
        for (int p = 0; p < 2; p++) {
            const int r = p * 32 + lr;
            *(float4*)&As[r][lk] = *(const float4*)&g_sent[s0 + r][k0 + lk];
            *(float4*)&Bs[r][lk] = *(const float4*)&Wih[(size_t)(gc0 + r) * 512 + k0 + lk];
        }
        __syncthreads();
#pragma unroll
        for (int k = 0; k < 32; k += 4) {
            ulonglong2 a_[4], b_[4];
#pragma unroll
            for (int i = 0; i < 4; i++) a_[i] = *(const ulonglong2*)&As[ty * 4 + i][k];
#pragma unroll
            for (int j = 0; j < 4; j++) b_[j] = *(const ulonglong2*)&Bs[tx + 16 * j][k];
#pragma unroll
            for (int i = 0; i < 4; i++)
#pragma unroll
                for (int j = 0; j < 4; j++) {
                    fma2(acc2[i][j], a_[i].x, b_[j].x);
                    fma2(acc2[i][j], a_[i].y, b_[j].y);
                }
        }
        __syncthreads();
    }
#pragma unroll
    for (int j = 0; j < 4; j++) {
        const int cgl = gc0 + tx + 16 * j;
        const float bj = bih[cgl];
#pragma unroll
        for (int i = 0; i < 4; i++) {
            float2 f = asf2(acc2[i][j]);
            g_sxg[dir][s0 + ty * 4 + i][cgl] = f.x + f.y + bj;
        }
    }
}

// ---------------- kernel 5: sentence recurrence (reg weights, DSMEM push + cluster barrier) -
// grid 16 = dir(2) x unit-tile(8 x 32 units) = 2 clusters of 8, 384 threads
// thread map: warp w (0..11), lane l: row r = w*8 + (l>>2) (0..95), K-quarter q = l&3
__global__ void __launch_bounds__(384) __cluster_dims__(8, 1, 1) k_sent_rec(
    const float* __restrict__ WhhF, const float* __restrict__ WhhB,
    const float* __restrict__ bhhF, const float* __restrict__ bhhB)
{
    __shared__ float hb[2][272];    // h buffers, quarter-padded: u -> (u>>6)*68 + (u&63)
    __shared__ float gv[96];        // gate values: r = gate*32 + ulocal
    const int dir = blockIdx.x >> 3;
    const int ut  = blockIdx.x & 7;
    const int u0  = ut * 32;
    const float* __restrict__ Whh = dir ? WhhB : WhhF;
    const float* __restrict__ bhh = dir ? bhhB : bhhF;
    const int tid = threadIdx.x;
    const int l = tid & 31;
    const int r = (tid >> 5) * 8 + (l >> 2);
    const int q = l & 3;
    const int row = (r >> 5) * 256 + u0 + (r & 31);
    const uint32_t hb_base = smem_u32(hb);

    ull wreg[32];
    {
        const float4* wsrc = (const float4*)&Whh[(size_t)row * 256 + q * 64];
#pragma unroll
        for (int i = 0; i < 16; i++) {
            float4 v = wsrc[i];
            wreg[2 * i]     = mkull(v.x, v.y);
            wreg[2 * i + 1] = mkull(v.z, v.w);
        }
    }
    const float bh = bhh[row];
    for (int k = tid; k < 544; k += 384) hb[0][k] = 0.0f;
    __syncthreads();
    asm volatile("barrier.cluster.arrive.aligned;" ::: "memory");
    asm volatile("barrier.cluster.wait.aligned;" ::: "memory");

    for (int t = 0; t < 256; t++) {
        const int tt = dir ? (255 - t) : t;
        const int cur = t & 1, nxt = cur ^ 1;
        float xr = 0.0f, xz = 0.0f, xn = 0.0f;
        if (tid < 32) {
            const int u = u0 + tid;
            xr = g_sxg[dir][tt][u];
            xz = g_sxg[dir][tt][256 + u];
            xn = g_sxg[dir][tt][512 + u];
        }
        ull acc2 = 0ull;
        const float* hq = &hb[cur][q * 68];
#pragma unroll
        for (int i = 0; i < 16; i++) {
            ulonglong2 h2 = *(const ulonglong2*)&hq[i * 4];
            fma2(acc2, h2.x, wreg[2 * i]);
            fma2(acc2, h2.y, wreg[2 * i + 1]);
        }
        float2 fa = asf2(acc2);
        float s = fa.x + fa.y;
        s += __shfl_xor_sync(0xffffffffu, s, 1);
        s += __shfl_xor_sync(0xffffffffu, s, 2);
        if (q == 0) gv[r] = s + bh;
        __syncthreads();
        if (tid < 32) {
            const int u = u0 + tid;
            const float hold = hb[cur][(u >> 6) * 68 + (u & 63)];
            const float rr = sigf(xr + gv[tid]);
            const float zz = sigf(xz + gv[32 + tid]);
            const float nn = tanh_fast(xn + rr * gv[64 + tid]);
            const float hnew = (1.0f - zz) * nn + zz * hold;
            g_sentout[tt][dir * 256 + u] = hnew;
            if (t < 255) {
                const uint32_t adr =
                    hb_base + (uint32_t)(nxt * 272 + (u >> 6) * 68 + (u & 63)) * 4u;
#pragma unroll
                for (int c = 0; c < 8; c++) sts_cluster(adr, (uint32_t)c, hnew);
            }
        }
        asm volatile("barrier.cluster.arrive.aligned;" ::: "memory");
        asm volatile("barrier.cluster.wait.aligned;" ::: "memory");
    }
}

// ---------------- kernel 6: sentence attention + classifier + softmax ----------------
__global__ void __launch_bounds__(256) k_doc(
    const float* __restrict__ attw, const float* __restrict__ attb,
    const float* __restrict__ clsW, const float* __restrict__ clsB,
    float* __restrict__ out)
{
    __shared__ float sc[256];
    __shared__ float red[8];
    __shared__ float docv[512];
    __shared__ float lg[10];
    const int tid = threadIdx.x, wp = tid >> 5, ln = tid & 31;
    const float bb = attb[0];
    for (int s = wp; s < 256; s += 8) {
        const float* op = &g_sentout[s][0];
        float d = 0.0f;
#pragma unroll
        for (int i = 0; i < 4; i++) {
            float4 o = *(const float4*)&op[ln * 16 + i * 4];
            float4 a = *(const float4*)&attw[ln * 16 + i * 4];
            d += o.x * a.x + o.y * a.y + o.z * a.z + o.w * a.w;
        }
#pragma unroll
        for (int off = 16; off > 0; off >>= 1) d += __shfl_xor_sync(0xffffffffu, d, off);
        if (ln == 0) sc[s] = tanhf(d + bb);
    }
    __syncthreads();
    float v = sc[tid];
    float m = v;
#pragma unroll
    for (int off = 16; off > 0; off >>= 1) m = fmaxf(m, __shfl_xor_sync(0xffffffffu, m, off));
    if (ln == 0) red[wp] = m;
    __syncthreads();
    if (tid < 8) {
        float mm = red[tid];
#pragma unroll
        for (int off = 4; off > 0; off >>= 1) mm = fmaxf(mm, __shfl_xor_sync(0xffu, mm, off));
        red[tid] = mm;
    }
    __syncthreads();
    const float gm = red[0];
    float e = expf(v - gm);
    float ssum = e;
#pragma unroll
    for (int off = 16; off > 0; off >>= 1) ssum += __shfl_xor_sync(0xffffffffu, ssum, off);
    __syncthreads();
    if (ln == 0) red[wp] = ssum;
    __syncthreads();
    if (tid < 8) {
        float s2 = red[tid];
#pragma unroll
        for (int off = 4; off > 0; off >>= 1) s2 += __shfl_xor_sync(0xffu, s2, off);
        red[tid] = s2;
    }
    __syncthreads();
    const float tot = red[0];
    sc[tid] = e / tot;
    __syncthreads();
    float a0 = 0.0f, a1 = 0.0f;
    for (int s = 0; s < 256; s++) {
        const float a = sc[s];
        a0 += a * g_sentout[s][tid];
        a1 += a * g_sentout[s][tid + 256];
    }
    docv[tid] = a0; docv[tid + 256] = a1;
    __syncthreads();
    for (int o = wp; o < 10; o += 8) {
        const float* wr = &clsW[o * 512];
        float d = 0.0f;
#pragma unroll
        for (int i = 0; i < 4; i++) {
            float4 x = *(const float4*)&docv[ln * 16 + i * 4];
            float4 w = *(const float4*)&wr[ln * 16 + i * 4];
            d += x.x * w.x + x.y * w.y + x.z * w.z + x.w * w.w;
        }
#pragma unroll
        for (int off = 16; off > 0; off >>= 1) d += __shfl_xor_sync(0xffffffffu, d, off);
        if (ln == 0) lg[o] = d + clsB[o];
    }
    __syncthreads();
    if (tid == 0) {
        float mm = lg[0];
        for (int i = 1; i < 10; i++) mm = fmaxf(mm, lg[i]);
        float s2 = 0.0f;
        float ee[10];
        for (int i = 0; i < 10; i++) { ee[i] = expf(lg[i] - mm); s2 += ee[i]; }
        for (int i = 0; i < 10; i++) out[i] = ee[i] / s2;
    }
}

// ---------------- launch ----------------
extern "C" void kernel_launch(void* const* d_in, const int* in_sizes, int n_in,
                              void* d_out, int out_size) {
    const int*   toks  = (const int*)d_in[0];
    const float* emb   = (const float*)d_in[1];
    const float* wWihF = (const float*)d_in[2];
    const float* wWhhF = (const float*)d_in[3];
    const float* wBihF = (const float*)d_in[4];
    const float* wBhhF = (const float*)d_in[5];
    const float* wWihB = (const float*)d_in[6];
    const float* wWhhB = (const float*)d_in[7];
    const float* wBihB = (const float*)d_in[8];
    const float* wBhhB = (const float*)d_in[9];
    const float* sWihF = (const float*)d_in[10];
    const float* sWhhF = (const float*)d_in[11];
    const float* sBihF = (const float*)d_in[12];
    const float* sBhhF = (const float*)d_in[13];
    const float* sWihB = (const float*)d_in[14];
    const float* sWhhB = (const float*)d_in[15];
    const float* sBihB = (const float*)d_in[16];
    const float* sBhhB = (const float*)d_in[17];
    const float* wAttW = (const float*)d_in[18];
    const float* wAttB = (const float*)d_in[19];
    const float* sAttW = (const float*)d_in[20];
    const float* sAttB = (const float*)d_in[21];
    const float* clsW  = (const float*)d_in[22];
    const float* clsB  = (const float*)d_in[23];
    float* out = (float*)d_out;

    const int WREC_SMEM = (2 * 32 * 388 + 32 * 256 + 2 * 128 * 25 + 96) * 4;  // 158080
    cudaFuncSetAttribute(k_word_rec, cudaFuncAttributeMaxDynamicSharedMemorySize, WREC_SMEM);

    k_zero_bars<<<1, 32>>>();
    k_zero_bars<<<1, 32>>>();                        // dummy: keeps gates at ncu slot (idx 3)
    k_cvt_wih<<<2 * G3 * EN / 256, 256>>>(wWihF, wWihB);
    dim3 g1(24, 256);
    k_word_gates<<<g1, 256>>>(toks, emb, wBihF, wBihB);
    k_word_rec<<<128, 256, WREC_SMEM>>>(wWhhF, wWhhB, wBhhF, wBhhB);
    k_word_attn<<<256, 256>>>(wAttW, wAttB);
    dim3 g2(24, 4);
    k_sent_gates<<<g2, 256>>>(sWihF, sWihB, sBihF, sBihB);
    k_sent_rec<<<16, 384>>>(sWhhF, sWhhB, sBhhF, sBhhB);
    k_doc<<<1, 256>>>(sAttW, sAttB, clsW, clsB, out);
}